// round 16
// baseline (speedup 1.0000x reference)
#include <cuda_runtime.h>
#include <cuda_fp16.h>
#include <cstdint>
#include <cstddef>

#define BB 32
#define NN 1024
#define MM 256
#define DD 512
#define NSPLIT 16

// -------------------- device scratch --------------------
__device__ __align__(128) __half g_E  [(size_t)BB * NN * MM];   // exp(S - colmax_blk), 0 for n>=clen
__device__ __align__(128) __half g_A  [(size_t)BB * NN * MM];
__device__ __align__(128) __half g_midT[(size_t)BB * DD * MM];  // mid^T [d][m] fp16
__device__ __align__(128) __half g_qs [(size_t)BB * MM * DD];   // (query*w_m) fp16
__device__ __align__(128) __half g_qT [(size_t)BB * DD * MM];   // query^T [d][m] fp16
__device__ __align__(128) __half g_ctxh[(size_t)BB * NN * DD];  // ctx fp16
__device__ float g_pmax[BB][NSPLIT][MM];
__device__ float g_psum[BB][NSPLIT][MM];
__device__ float g_cw[BB * NN];
__device__ float g_qw[BB * MM];
__device__ int   g_clen[BB];
__device__ int   g_qlen[BB];

// -------------------- helpers --------------------
__device__ __forceinline__ void mma16(float* c, const uint32_t* a, uint32_t b0, uint32_t b1) {
    asm volatile(
        "mma.sync.aligned.m16n8k16.row.col.f32.f16.f16.f32 "
        "{%0,%1,%2,%3}, {%4,%5,%6,%7}, {%8,%9}, {%0,%1,%2,%3};"
        : "+f"(c[0]), "+f"(c[1]), "+f"(c[2]), "+f"(c[3])
        : "r"(a[0]), "r"(a[1]), "r"(a[2]), "r"(a[3]), "r"(b0), "r"(b1));
}

__device__ __forceinline__ void ldsm4(uint32_t* r, uint32_t addr) {
    asm volatile("ldmatrix.sync.aligned.m8n8.x4.shared.b16 {%0,%1,%2,%3}, [%4];"
                 : "=r"(r[0]), "=r"(r[1]), "=r"(r[2]), "=r"(r[3]) : "r"(addr));
}
__device__ __forceinline__ void ldsm4t(uint32_t* r, uint32_t addr) {
    asm volatile("ldmatrix.sync.aligned.m8n8.x4.trans.shared.b16 {%0,%1,%2,%3}, [%4];"
                 : "=r"(r[0]), "=r"(r[1]), "=r"(r[2]), "=r"(r[3]) : "r"(addr));
}
__device__ __forceinline__ uint32_t hmul2u(uint32_t a, uint32_t b) {
    uint32_t r;
    asm("mul.f16x2 %0, %1, %2;" : "=r"(r) : "r"(a), "r"(b));
    return r;
}

__device__ __forceinline__ uint32_t s2u(const void* p) {
    return (uint32_t)__cvta_generic_to_shared(p);
}
__device__ __forceinline__ void cp16(uint32_t dst, const void* src) {
    asm volatile("cp.async.cg.shared.global [%0], [%1], 16;" :: "r"(dst), "l"(src));
}
__device__ __forceinline__ void cp_commit() { asm volatile("cp.async.commit_group;"); }
__device__ __forceinline__ void cp_wait1()  { asm volatile("cp.async.wait_group 1;"); }
__device__ __forceinline__ void cp_wait0()  { asm volatile("cp.async.wait_group 0;"); }

// -------------------- mask length detection --------------------
__device__ __forceinline__ int count_prefix(const unsigned char* p, int length,
                                            int esize, unsigned val) {
    int c = 0;
    for (int i = 0; i < length; i++) {
        unsigned v;
        if (esize == 1)      v = p[i];
        else if (esize == 2) v = ((const unsigned short*)p)[i];
        else                 v = ((const unsigned*)p)[i];
        if (v != val) break;
        c++;
    }
    return c;
}

__device__ void detect_fmt(const unsigned char* p, int length, int minlen,
                           int* esize, unsigned* val) {
    const int es[4]      = {1, 2, 4, 4};
    const unsigned vv[4] = {1u, 0x3F80u, 1u, 0x3F800000u};
    for (int k = 0; k < 4; k++) {
        if (count_prefix(p, length, es[k], vv[k]) >= minlen) {
            *esize = es[k]; *val = vv[k]; return;
        }
    }
    *esize = 4; *val = 1u;
}

__global__ void k_lens(const unsigned char* __restrict__ cm,
                       const unsigned char* __restrict__ qm) {
    __shared__ int es_c, es_q;
    __shared__ unsigned v_c, v_q;
    int t = threadIdx.x;
    if (t == 0) detect_fmt(cm, NN, NN / 4, &es_c, &v_c);
    if (t == 1) detect_fmt(qm, MM, MM / 4, &es_q, &v_q);
    __syncthreads();
    if (t < BB) {
        g_clen[t] = count_prefix(cm + (size_t)t * NN * es_c, NN, es_c, v_c);
    } else if (t < 2 * BB) {
        int b = t - BB;
        g_qlen[b] = count_prefix(qm + (size_t)b * MM * es_q, MM, es_q, v_q);
    }
}

// ------------- cw = ctx @ w_c (also emits ctx fp16), qw = query @ w_q ------------
__global__ void __launch_bounds__(256) k_rowdots(const float* __restrict__ ctx,
                                                 const float* __restrict__ qry,
                                                 const float* __restrict__ w) {
    int warp = threadIdx.x >> 5, lane = threadIdx.x & 31;
    int row = blockIdx.x * 8 + warp;
    if (row < BB * NN) {
        const float* src = ctx + (size_t)row * DD;
        const float* wp  = w + DD;
        __half* hdst = g_ctxh + (size_t)row * DD;
        float s = 0.f;
        #pragma unroll
        for (int d = lane * 4; d < DD; d += 128) {
            float4 v  = *(const float4*)(src + d);
            float4 wv = *(const float4*)(wp + d);
            s += v.x * wv.x + v.y * wv.y + v.z * wv.z + v.w * wv.w;
            __half2* hp = (__half2*)(hdst + d);
            hp[0] = __floats2half2_rn(v.x, v.y);
            hp[1] = __floats2half2_rn(v.z, v.w);
        }
        #pragma unroll
        for (int o = 16; o; o >>= 1) s += __shfl_xor_sync(0xFFFFFFFFu, s, o);
        if (lane == 0) g_cw[row] = s;
    } else {
        int r = row - BB * NN;
        const float* src = qry + (size_t)r * DD;
        float s = 0.f;
        #pragma unroll
        for (int d = lane * 4; d < DD; d += 128) {
            float4 v  = *(const float4*)(src + d);
            float4 wv = *(const float4*)(w + d);
            s += v.x * wv.x + v.y * wv.y + v.z * wv.z + v.w * wv.w;
        }
        #pragma unroll
        for (int o = 16; o; o >>= 1) s += __shfl_xor_sync(0xFFFFFFFFu, s, o);
        if (lane == 0) g_qw[r] = s;
    }
}

// ----- k_q: one pass over qry -> qT[d][m] fp16 (transposed) + qs[m][d] fp16 ------
__global__ void k_q(const float* __restrict__ qry, const float* __restrict__ w) {
    __shared__ float t[32][33];
    int b = blockIdx.z, m0 = blockIdx.x * 32, d0 = blockIdx.y * 32;
    int tx = threadIdx.x, ty = threadIdx.y;
    const float* src = qry + ((size_t)b * MM + m0) * DD + d0;
    float wmv = w[2 * DD + d0 + tx];
    #pragma unroll
    for (int i = 0; i < 4; i++) {
        float v = src[(size_t)(ty + 8 * i) * DD + tx];
        t[ty + 8 * i][tx] = v;
        g_qs[((size_t)b * MM + m0 + ty + 8 * i) * DD + d0 + tx] = __float2half_rn(v * wmv);
    }
    __syncthreads();
    __half* dst = g_qT + ((size_t)b * DD + d0) * MM + m0;
    #pragma unroll
    for (int i = 0; i < 4; i++)
        dst[(size_t)(ty + 8 * i) * MM + tx] = __float2half_rn(t[tx][ty + 8 * i]);
}

// ============ k_S_f: S = ctx.qs^T (64n x 256m), 256thr, 2-stage ==================
// Epilogue anchored at column max over ALL block rows (fc always finite):
// E = exp(s-fc) (0 stored for invalid rows); A = E*exp(fc)/rowsum(E*exp(fc)).
#define S_STGB 46080               // (64 + 256) * 144
#define S_BOFFB 9216               // 64 * 144
#define S_REDF (2 * S_STGB / 4)
__global__ void __launch_bounds__(256) k_S_f() {
    extern __shared__ float sm[];
    float* rowred  = sm + S_REDF;          // [4][64]
    float* colred  = rowred + 256;         // [2][256]
    float* colred2 = colred + 512;         // [2][256]
    float* cw_s    = colred2 + 512;        // [64]
    float* qw_s    = cw_s + 64;            // [256]

    int b = blockIdx.y, n0 = blockIdx.x * 64;
    int tid = threadIdx.x, lane = tid & 31, warp = tid >> 5;
    int wn = warp & 1, wm = warp >> 1;
    uint32_t smb = s2u(sm);

    if (tid < 64) cw_s[tid] = g_cw[b * NN + n0 + tid];
    qw_s[tid] = g_qw[b * MM + tid];

    const __half* ctxb = g_ctxh + ((size_t)b * NN + n0) * DD;
    const __half* qsb  = g_qs   + (size_t)b * MM * DD;

    uint32_t aLd[2], bLd[4];
    #pragma unroll
    for (int i = 0; i < 2; i++)
        aLd[i] = smb + (wn * 32 + i * 16 + (lane & 15)) * 144 + (lane >> 4) * 16;
    #pragma unroll
    for (int jj = 0; jj < 4; jj++)
        bLd[jj] = smb + S_BOFFB + (wm * 64 + jj * 16 + (lane & 15)) * 144 + (lane >> 4) * 16;

    float acc[2][8][4] = {};
    const int KT = DD / 64;  // 8

    #define SF_LOAD(kt, s) do { \
        uint32_t base = smb + (s) * S_STGB; \
        _Pragma("unroll") \
        for (int r2 = 0; r2 < 2; r2++) { \
            int idx = tid + 256 * r2; int row = idx >> 3, c = idx & 7; \
            cp16(base + row * 144 + c * 16, ctxb + (size_t)row * DD + (kt) * 64 + c * 8); \
        } \
        _Pragma("unroll") \
        for (int r2 = 0; r2 < 8; r2++) { \
            int idx = tid + 256 * r2; int row = idx >> 3, c = idx & 7; \
            cp16(base + S_BOFFB + row * 144 + c * 16, qsb + (size_t)row * DD + (kt) * 64 + c * 8); \
        } \
    } while (0)

    SF_LOAD(0, 0); cp_commit();

    for (int kt = 0; kt < KT; kt++) {
        if (kt + 1 < KT) { SF_LOAD(kt + 1, (kt + 1) & 1); cp_commit(); cp_wait1(); }
        else             { cp_wait0(); }
        __syncthreads();
        uint32_t boff = (kt & 1) * S_STGB;
        #pragma unroll
        for (int kk = 0; kk < 4; kk++) {
            uint32_t ko = boff + kk * 32;
            uint32_t a0[4], a1[4];
            ldsm4(a0, aLd[0] + ko);
            ldsm4(a1, aLd[1] + ko);
            #pragma unroll
            for (int jj = 0; jj < 4; jj++) {
                uint32_t bb[4];
                ldsm4(bb, bLd[jj] + ko);
                mma16(acc[0][2 * jj],     a0, bb[0], bb[2]);
                mma16(acc[0][2 * jj + 1], a0, bb[1], bb[3]);
                mma16(acc[1][2 * jj],     a1, bb[0], bb[2]);
                mma16(acc[1][2 * jj + 1], a1, bb[1], bb[3]);
            }
        }
        __syncthreads();
    }
    #undef SF_LOAD

    // ======== fused epilogue (col-max anchored, fc over ALL rows) ========
    int qlen = g_qlen[b], clen = g_clen[b];
    int rbase = wn * 32 + (lane >> 2);
    int cbase = wm * 64 + 2 * (lane & 3);

    // pass 1: per-column block max over ALL 64 rows (finite always)
    #pragma unroll
    for (int j = 0; j < 8; j++) {
        #pragma unroll
        for (int e2 = 0; e2 < 2; e2++) {
            int c = cbase + j * 8 + e2;
            float cm = -1e30f;
            #pragma unroll
            for (int i = 0; i < 2; i++)
                #pragma unroll
                for (int h = 0; h < 2; h++) {
                    int r = rbase + i * 16 + h * 8;
                    cm = fmaxf(cm, acc[i][j][h * 2 + e2] + cw_s[r] + qw_s[c]);
                }
            #pragma unroll
            for (int o = 4; o <= 16; o <<= 1)
                cm = fmaxf(cm, __shfl_xor_sync(0xFFFFFFFFu, cm, o));
            if ((lane >> 2) == 0) colred[wn * 256 + c] = cm;
        }
    }
    __syncthreads();

    // pass 2: E = exp(s - fc) (kept in acc), E store (0 if invalid row),
    //         col sums (valid rows only), row sums of E*exp(fc) (all rows)
    float uc[8][2];
    float rs[2][2] = {};
    #pragma unroll
    for (int j = 0; j < 8; j++) {
        int c = cbase + j * 8;
        float fc0 = fmaxf(colred[c],     colred[256 + c]);
        float fc1 = fmaxf(colred[c + 1], colred[256 + c + 1]);
        uc[j][0] = __expf(fc0);
        uc[j][1] = __expf(fc1);
        bool q0 = (c < qlen), q1 = (c + 1 < qlen);
        float cs0 = 0.f, cs1 = 0.f;
        #pragma unroll
        for (int i = 0; i < 2; i++)
            #pragma unroll
            for (int h = 0; h < 2; h++) {
                int r = rbase + i * 16 + h * 8;
                bool valid = (n0 + r < clen);
                float cwv = cw_s[r];
                float e0 = __expf(acc[i][j][h * 2]     + cwv + qw_s[c]     - fc0);
                float e1 = __expf(acc[i][j][h * 2 + 1] + cwv + qw_s[c + 1] - fc1);
                acc[i][j][h * 2]     = e0;
                acc[i][j][h * 2 + 1] = e1;
                __half* Erow = g_E + ((size_t)b * NN + n0 + r) * MM;
                *(__half2*)(Erow + c) = __floats2half2_rn(valid ? e0 : 0.f, valid ? e1 : 0.f);
                if (valid) { cs0 += e0; cs1 += e1; }
                rs[i][h] += (q0 ? e0 * uc[j][0] : 0.f) + (q1 ? e1 * uc[j][1] : 0.f);
            }
        #pragma unroll
        for (int o = 4; o <= 16; o <<= 1) {
            cs0 += __shfl_xor_sync(0xFFFFFFFFu, cs0, o);
            cs1 += __shfl_xor_sync(0xFFFFFFFFu, cs1, o);
        }
        if ((lane >> 2) == 0) {
            colred2[wn * 256 + c]     = cs0;
            colred2[wn * 256 + c + 1] = cs1;
        }
    }
    #pragma unroll
    for (int i = 0; i < 2; i++)
        #pragma unroll
        for (int h = 0; h < 2; h++) {
            #pragma unroll
            for (int o = 1; o <= 2; o <<= 1)
                rs[i][h] += __shfl_xor_sync(0xFFFFFFFFu, rs[i][h], o);
        }
    if ((lane & 3) == 0) {
        #pragma unroll
        for (int i = 0; i < 2; i++)
            #pragma unroll
            for (int h = 0; h < 2; h++)
                rowred[wm * 64 + rbase + i * 16 + h * 8] = rs[i][h];
    }
    __syncthreads();

    // pass 3a: column partials to global
    if (wn == 0 && (lane >> 2) == 0) {
        #pragma unroll
        for (int j = 0; j < 8; j++)
            #pragma unroll
            for (int e2 = 0; e2 < 2; e2++) {
                int c = cbase + j * 8 + e2;
                float fm2 = fmaxf(colred[c], colred[256 + c]);
                float ps  = colred2[c] + colred2[256 + c];
                g_pmax[b][blockIdx.x][c] = fm2;
                g_psum[b][blockIdx.x][c] = ps;
            }
    }

    // pass 3b: rinv and A = E * uc * rinv
    float rinv[2][2];
    #pragma unroll
    for (int i = 0; i < 2; i++)
        #pragma unroll
        for (int h = 0; h < 2; h++) {
            int r = rbase + i * 16 + h * 8;
            float t = 0.f;
            #pragma unroll
            for (int q = 0; q < 4; q++) t += rowred[q * 64 + r];
            rinv[i][h] = 1.f / t;
        }
    #pragma unroll
    for (int i = 0; i < 2; i++)
        #pragma unroll
        for (int h = 0; h < 2; h++) {
            int r = rbase + i * 16 + h * 8;
            __half* Arow = g_A + ((size_t)b * NN + n0 + r) * MM;
            #pragma unroll
            for (int j = 0; j < 8; j++) {
                int c = cbase + j * 8;
                float a0 = (c < qlen)     ? acc[i][j][h * 2]     * uc[j][0] * rinv[i][h] : 0.f;
                float a1 = (c + 1 < qlen) ? acc[i][j][h * 2 + 1] * uc[j][1] * rinv[i][h] : 0.f;
                *(__half2*)(Arow + c) = __floats2half2_rn(a0, a1);
            }
        }
}

// ==== k_mid_f: midT[d][m] = ((E*sc)^T @ ctx)^T, 256thr, 128m x 64d, BK=64 ========
#define M_STGB 26624               // E 64x272 (17408) + ctx 64x144 (9216)
#define M_BOFFB 17408
__global__ void __launch_bounds__(256) k_mid_f() {
    extern __shared__ float sm[];
    uint32_t smb = s2u(sm);
    uint32_t* scs = (uint32_t*)((char*)sm + 2 * M_STGB);   // [NSPLIT][128]

    int b = blockIdx.z, d0 = blockIdx.x * 64, m0 = blockIdx.y * 128;
    int tid = threadIdx.x, lane = tid & 31, warp = tid >> 5;
    int wm = warp & 3, wd = warp >> 2;

    if (tid < 128) {
        int m = m0 + tid;
        float fm = -1e30f;
        #pragma unroll
        for (int q = 0; q < NSPLIT; q++) fm = fmaxf(fm, g_pmax[b][q][m]);
        float fs = 0.f;
        #pragma unroll
        for (int q = 0; q < NSPLIT; q++)
            fs += g_psum[b][q][m] * __expf(g_pmax[b][q][m] - fm);
        float inv = 1.f / fs;
        #pragma unroll
        for (int q = 0; q < NSPLIT; q++) {
            float s = __expf(g_pmax[b][q][m] - fm) * inv;
            __half2 h2 = __half2half2(__float2half_rn(s));
            scs[q * 128 + tid] = *(uint32_t*)&h2;
        }
    }

    const __half* Eb   = g_E    + (size_t)b * NN * MM;
    const __half* ctxb = g_ctxh + (size_t)b * NN * DD;

    int lr = lane & 7, g = lane >> 3;
    uint32_t aLd[2], bLd[2];
    #pragma unroll
    for (int i = 0; i < 2; i++)
        aLd[i] = smb + (lr + (g >> 1) * 8) * 272 + (wm * 32 + i * 16 + (g & 1) * 8) * 2;
    #pragma unroll
    for (int j = 0; j < 2; j++)
        bLd[j] = smb + M_BOFFB + (lr + (g & 1) * 8) * 144 + (wd * 32 + j * 16 + (g >> 1) * 8) * 2;

    float acc[2][4][4] = {};
    const int KT = NN / 64;  // 16

    #define MF_LOAD(kt, s) do { \
        uint32_t base = smb + (s) * M_STGB; \
        _Pragma("unroll") \
        for (int r2 = 0; r2 < 4; r2++) { \
            int idx = tid + 256 * r2; int row = idx >> 4, c = idx & 15; \
            cp16(base + row * 272 + c * 16, Eb + (size_t)((kt) * 64 + row) * MM + m0 + c * 8); \
        } \
        _Pragma("unroll") \
        for (int r2 = 0; r2 < 2; r2++) { \
            int idx = tid + 256 * r2; int row = idx >> 3, c = idx & 7; \
            cp16(base + M_BOFFB + row * 144 + c * 16, ctxb + (size_t)((kt) * 64 + row) * DD + d0 + c * 8); \
        } \
    } while (0)

    MF_LOAD(0, 0); cp_commit();

    for (int kt = 0; kt < KT; kt++) {
        if (kt + 1 < KT) { MF_LOAD(kt + 1, (kt + 1) & 1); cp_commit(); cp_wait1(); }
        else             { cp_wait0(); }
        __syncthreads();
        uint32_t base = (kt & 1) * M_STGB;
        uint32_t sc00 = scs[kt * 128 + wm * 32 + (lane >> 2)];
        uint32_t sc01 = scs[kt * 128 + wm * 32 + (lane >> 2) + 8];
        uint32_t sc10 = scs[kt * 128 + wm * 32 + 16 + (lane >> 2)];
        uint32_t sc11 = scs[kt * 128 + wm * 32 + 16 + (lane >> 2) + 8];
        #pragma unroll
        for (int step = 0; step < 4; step++) {
            uint32_t koA = base + step * 16 * 272;
            uint32_t koB = base + step * 16 * 144;
            uint32_t a[2][4];
            ldsm4t(a[0], aLd[0] + koA);
            ldsm4t(a[1], aLd[1] + koA);
            a[0][0] = hmul2u(a[0][0], sc00); a[0][2] = hmul2u(a[0][2], sc00);
            a[0][1] = hmul2u(a[0][1], sc01); a[0][3] = hmul2u(a[0][3], sc01);
            a[1][0] = hmul2u(a[1][0], sc10); a[1][2] = hmul2u(a[1][2], sc10);
            a[1][1] = hmul2u(a[1][1], sc11); a[1][3] = hmul2u(a[1][3], sc11);
            #pragma unroll
            for (int j = 0; j < 2; j++) {
                uint32_t bb[4];
                ldsm4t(bb, bLd[j] + koB);
                #pragma unroll
                for (int i = 0; i < 2; i++) {
                    mma16(acc[i][j * 2],     a[i], bb[0], bb[1]);
                    mma16(acc[i][j * 2 + 1], a[i], bb[2], bb[3]);
                }
            }
        }
        __syncthreads();
    }
    #undef MF_LOAD

    __half* ot = (__half*)sm;
    #pragma unroll
    for (int i = 0; i < 2; i++) {
        int m_r = wm * 32 + i * 16 + (lane >> 2);
        #pragma unroll
        for (int j = 0; j < 4; j++) {
            int c = wd * 32 + j * 8 + 2 * (lane & 3);
            ot[(size_t)c * 136 + m_r]           = __float2half_rn(acc[i][j][0]);
            ot[(size_t)(c + 1) * 136 + m_r]     = __float2half_rn(acc[i][j][1]);
            ot[(size_t)c * 136 + m_r + 8]       = __float2half_rn(acc[i][j][2]);
            ot[(size_t)(c + 1) * 136 + m_r + 8] = __float2half_rn(acc[i][j][3]);
        }
    }
    __syncthreads();
    #pragma unroll
    for (int rep = 0; rep < 4; rep++) {
        int idx = tid + rep * 256;
        int d = idx >> 4, m8 = (idx & 15) * 8;
        uint4 v = *(uint4*)(ot + (size_t)d * 136 + m8);
        *(uint4*)(g_midT + ((size_t)b * DD + d0 + d) * MM + m0 + m8) = v;
    }
}

// ======== k_out_f: 128n x 128d (2 x 64d subs), A resident full-K, 2-stage B ======
// smem: A [128][264]h = 67584B; B stages at 67584 + s*18432 (Bq 9216 + Bm 9216).
// 256 thr, warps: wn=warp&3 (32n), wd=warp>>2 (32d). 2 CTA/SM.
#define OA_ROWB 528
#define OB_BASE 67584
#define OB_STG  18432
__global__ void __launch_bounds__(256) k_out_f(const float* __restrict__ ctx,
                                               float* __restrict__ out) {
    extern __shared__ float sm[];
    int b = blockIdx.z, d0 = blockIdx.x * 128, n0 = blockIdx.y * 128;
    int tid = threadIdx.x, lane = tid & 31, warp = tid >> 5;
    int wn = warp & 3, wd = warp >> 2;
    uint32_t smb = s2u(sm);

    const __half* Ab  = g_A    + ((size_t)b * NN + n0) * MM;
    const __half* qTb = g_qT   + ((size_t)b * DD + d0) * MM;
    const __half* mTb = g_midT + ((size_t)b * DD + d0) * MM;

    // A full-K load: 16 cp16 per thread
    #pragma unroll
    for (int r2 = 0; r2 < 16; r2++) {
        int idx = tid + 256 * r2;
        int row = idx >> 5, c = idx & 31;
        cp16(smb + row * OA_ROWB + c * 16, Ab + (size_t)row * MM + c * 8);
    }

    // B stage loader: it = dsub*4 + kt
    #define OB_LOAD(it, s) do { \
        int dsub = (it) >> 2, kt = (it) & 3; \
        uint32_t base = smb + OB_BASE + (s) * OB_STG; \
        _Pragma("unroll") \
        for (int r2 = 0; r2 < 2; r2++) { \
            int idx = tid + 256 * r2; int row = idx >> 3, c = idx & 7; \
            uint32_t o = base + row * 144 + c * 16; \
            size_t go = (size_t)(dsub * 64 + row) * MM + kt * 64 + c * 8; \
            cp16(o,        qTb + go); \
            cp16(o + 9216, mTb + go); \
        } \
    } while (0)

    OB_LOAD(0, 0); cp_commit();

    uint32_t aLd[2], bqLd[2], bmLd[2];
    #pragma unroll
    for (int i = 0; i < 2; i++)
        aLd[i] = smb + (wn * 32 + i * 16 + (lane & 15)) * OA_ROWB + (lane >> 4) * 16;
    #pragma unroll
    for (int jj = 0; jj < 2; jj++) {
        bqLd[jj] = smb + OB_BASE + (wd * 32 + jj * 16 + (lane & 15)) * 144 + (lane >> 4) * 16;
        bmLd[jj] = bqLd[jj] + 9216;
    }

    float accq[2][4][4] = {};
    float accm[2][4][4] = {};

    for (int it = 0; it < 8; it++) {
        if (it + 1 < 8) { OB_LOAD(it + 1, (it + 1) & 1); cp_commit(); cp_wait1(); }
        else            { cp_wait0(); }
        __syncthreads();
        uint32_t soff = (it & 1) * OB_STG;
        uint32_t aoff = (it & 3) * 128;   // kt*64 halfs = kt*128 bytes
        #pragma unroll
        for (int kk = 0; kk < 4; kk++) {
            uint32_t koA = aoff + kk * 32;
            uint32_t koB = soff + kk * 32;
            uint32_t a0[4], a1[4];
            ldsm4(a0, aLd[0] + koA);
            ldsm4(a1, aLd[1] + koA);
            #pragma unroll
            for (int jj = 0; jj < 2; jj++) {
                uint32_t bq[4], bm[4];
                ldsm4(bq, bqLd[jj] + koB);
                mma16(accq[0][jj * 2],     a0, bq[0], bq[2]);
                mma16(accq[0][jj * 2 + 1], a0, bq[1], bq[3]);
                mma16(accq[1][jj * 2],     a1, bq[0], bq[2]);
                mma16(accq[1][jj * 2 + 1], a1, bq[1], bq[3]);
                ldsm4(bm, bmLd[jj] + koB);
                mma16(accm[0][jj * 2],     a0, bm[0], bm[2]);
                mma16(accm[0][jj * 2 + 1], a0, bm[1], bm[3]);
                mma16(accm[1][jj * 2],     a1, bm[0], bm[2]);
                mma16(accm[1][jj * 2 + 1], a1, bm[1], bm[3]);
            }
        }
        __syncthreads();

        if ((it & 3) == 3) {
            // epilogue for dsub = it>>2: out = [ctx, c2q, ctx*c2q, ctx*q2c]
            int dsb = (it >> 2) * 64;
            #pragma unroll
            for (int i = 0; i < 2; i++) {
                #pragma unroll
                for (int half = 0; half < 2; half++) {
                    int n = n0 + wn * 32 + i * 16 + (lane >> 2) + half * 8;
                    const float* crow = ctx + ((size_t)b * NN + n) * DD;
                    float* orow = out + ((size_t)b * NN + n) * (4 * DD);
                    #pragma unroll
                    for (int ai = 0; ai < 4; ai++) {
                        int d = d0 + dsb + wd * 32 + ai * 8 + 2 * (lane & 3);
                        float2 cv = *(const float2*)(crow + d);
                        float c2q0 = accq[i][ai][half * 2], c2q1 = accq[i][ai][half * 2 + 1];
                        float q2c0 = accm[i][ai][half * 2], q2c1 = accm[i][ai][half * 2 + 1];
                        *(float2*)(orow + d)          = cv;
                        *(float2*)(orow + DD + d)     = make_float2(c2q0, c2q1);
                        *(float2*)(orow + 2 * DD + d) = make_float2(cv.x * c2q0, cv.y * c2q1);
                        *(float2*)(orow + 3 * DD + d) = make_float2(cv.x * q2c0, cv.y * q2c1);
                    }
                }
            }
            #pragma unroll
            for (int i = 0; i < 2; i++)
                #pragma unroll
                for (int ai = 0; ai < 4; ai++)
                    #pragma unroll
                    for (int e = 0; e < 4; e++) {
                        accq[i][ai][e] = 0.f;
                        accm[i][ai][e] = 0.f;
                    }
        }
    }
    #undef OB_LOAD
}

// -------------------- launch --------------------
extern "C" void kernel_launch(void* const* d_in, const int* in_sizes, int n_in,
                              void* d_out, int out_size) {
    const float* ctx = (const float*)d_in[0];
    const float* qry = (const float*)d_in[1];
    const unsigned char* cm = (const unsigned char*)d_in[2];
    const unsigned char* qm = (const unsigned char*)d_in[3];
    const float* w = (const float*)d_in[4];
    float* out = (float*)d_out;

    const int SMEM_S   = 2 * S_STGB + 1600 * 4;               // 98560
    const int SMEM_MID = 2 * M_STGB + NSPLIT * 128 * 4;       // 61440
    const int SMEM_OUT = OB_BASE + 2 * OB_STG;                // 104448

    cudaFuncSetAttribute(k_S_f,   cudaFuncAttributeMaxDynamicSharedMemorySize, SMEM_S);
    cudaFuncSetAttribute(k_mid_f, cudaFuncAttributeMaxDynamicSharedMemorySize, SMEM_MID);
    cudaFuncSetAttribute(k_out_f, cudaFuncAttributeMaxDynamicSharedMemorySize, SMEM_OUT);

    k_lens<<<1, 64>>>(cm, qm);
    k_rowdots<<<(BB * NN + BB * MM) / 8, 256>>>(ctx, qry, w);
    k_q<<<dim3(MM / 32, DD / 32, BB), dim3(32, 8)>>>(qry, w);
    k_S_f<<<dim3(NN / 64, BB), 256, SMEM_S>>>();
    k_mid_f<<<dim3(DD / 64, MM / 128, BB), 256, SMEM_MID>>>();
    k_out_f<<<dim3(DD / 128, NN / 128, BB), 256, SMEM_OUT>>>(ctx, out);
}

// round 17
// speedup vs baseline: 1.0520x; 1.0520x over previous
#include <cuda_runtime.h>
#include <cuda_fp16.h>
#include <cstdint>
#include <cstddef>

#define BB 32
#define NN 1024
#define MM 256
#define DD 512
#define NSPLIT 16

// -------------------- device scratch --------------------
__device__ __align__(128) __half g_E  [(size_t)BB * NN * MM];   // exp(S - colmax_blk), 0 for n>=clen
__device__ __align__(128) __half g_A  [(size_t)BB * NN * MM];
__device__ __align__(128) __half g_midT[(size_t)BB * DD * MM];  // mid^T [d][m] fp16
__device__ __align__(128) __half g_qs [(size_t)BB * MM * DD];   // (query*w_m) fp16
__device__ __align__(128) __half g_qT [(size_t)BB * DD * MM];   // query^T [d][m] fp16
__device__ __align__(128) __half g_ctxh[(size_t)BB * NN * DD];  // ctx fp16
__device__ float g_pmax[BB][NSPLIT][MM];
__device__ float g_psum[BB][NSPLIT][MM];
__device__ float g_cw[BB * NN];
__device__ float g_qw[BB * MM];
__device__ int   g_clen[BB];
__device__ int   g_qlen[BB];

// -------------------- helpers --------------------
__device__ __forceinline__ void mma16(float* c, const uint32_t* a, uint32_t b0, uint32_t b1) {
    asm volatile(
        "mma.sync.aligned.m16n8k16.row.col.f32.f16.f16.f32 "
        "{%0,%1,%2,%3}, {%4,%5,%6,%7}, {%8,%9}, {%0,%1,%2,%3};"
        : "+f"(c[0]), "+f"(c[1]), "+f"(c[2]), "+f"(c[3])
        : "r"(a[0]), "r"(a[1]), "r"(a[2]), "r"(a[3]), "r"(b0), "r"(b1));
}

__device__ __forceinline__ void ldsm4(uint32_t* r, uint32_t addr) {
    asm volatile("ldmatrix.sync.aligned.m8n8.x4.shared.b16 {%0,%1,%2,%3}, [%4];"
                 : "=r"(r[0]), "=r"(r[1]), "=r"(r[2]), "=r"(r[3]) : "r"(addr));
}
__device__ __forceinline__ void ldsm4t(uint32_t* r, uint32_t addr) {
    asm volatile("ldmatrix.sync.aligned.m8n8.x4.trans.shared.b16 {%0,%1,%2,%3}, [%4];"
                 : "=r"(r[0]), "=r"(r[1]), "=r"(r[2]), "=r"(r[3]) : "r"(addr));
}
__device__ __forceinline__ uint32_t hmul2u(uint32_t a, uint32_t b) {
    uint32_t r;
    asm("mul.f16x2 %0, %1, %2;" : "=r"(r) : "r"(a), "r"(b));
    return r;
}

__device__ __forceinline__ uint32_t s2u(const void* p) {
    return (uint32_t)__cvta_generic_to_shared(p);
}
__device__ __forceinline__ void cp16(uint32_t dst, const void* src) {
    asm volatile("cp.async.cg.shared.global [%0], [%1], 16;" :: "r"(dst), "l"(src));
}
__device__ __forceinline__ void cp_commit() { asm volatile("cp.async.commit_group;"); }
__device__ __forceinline__ void cp_wait1()  { asm volatile("cp.async.wait_group 1;"); }
__device__ __forceinline__ void cp_wait0()  { asm volatile("cp.async.wait_group 0;"); }

// -------------------- mask length detection --------------------
__device__ __forceinline__ int count_prefix(const unsigned char* p, int length,
                                            int esize, unsigned val) {
    int c = 0;
    for (int i = 0; i < length; i++) {
        unsigned v;
        if (esize == 1)      v = p[i];
        else if (esize == 2) v = ((const unsigned short*)p)[i];
        else                 v = ((const unsigned*)p)[i];
        if (v != val) break;
        c++;
    }
    return c;
}

__device__ void detect_fmt(const unsigned char* p, int length, int minlen,
                           int* esize, unsigned* val) {
    const int es[4]      = {1, 2, 4, 4};
    const unsigned vv[4] = {1u, 0x3F80u, 1u, 0x3F800000u};
    for (int k = 0; k < 4; k++) {
        if (count_prefix(p, length, es[k], vv[k]) >= minlen) {
            *esize = es[k]; *val = vv[k]; return;
        }
    }
    *esize = 4; *val = 1u;
}

__global__ void k_lens(const unsigned char* __restrict__ cm,
                       const unsigned char* __restrict__ qm) {
    __shared__ int es_c, es_q;
    __shared__ unsigned v_c, v_q;
    int t = threadIdx.x;
    if (t == 0) detect_fmt(cm, NN, NN / 4, &es_c, &v_c);
    if (t == 1) detect_fmt(qm, MM, MM / 4, &es_q, &v_q);
    __syncthreads();
    if (t < BB) {
        g_clen[t] = count_prefix(cm + (size_t)t * NN * es_c, NN, es_c, v_c);
    } else if (t < 2 * BB) {
        int b = t - BB;
        g_qlen[b] = count_prefix(qm + (size_t)b * MM * es_q, MM, es_q, v_q);
    }
}

// ------------- cw = ctx @ w_c (also emits ctx fp16), qw = query @ w_q ------------
__global__ void __launch_bounds__(256) k_rowdots(const float* __restrict__ ctx,
                                                 const float* __restrict__ qry,
                                                 const float* __restrict__ w) {
    int warp = threadIdx.x >> 5, lane = threadIdx.x & 31;
    int row = blockIdx.x * 8 + warp;
    if (row < BB * NN) {
        const float* src = ctx + (size_t)row * DD;
        const float* wp  = w + DD;
        __half* hdst = g_ctxh + (size_t)row * DD;
        float s = 0.f;
        #pragma unroll
        for (int d = lane * 4; d < DD; d += 128) {
            float4 v  = *(const float4*)(src + d);
            float4 wv = *(const float4*)(wp + d);
            s += v.x * wv.x + v.y * wv.y + v.z * wv.z + v.w * wv.w;
            __half2* hp = (__half2*)(hdst + d);
            hp[0] = __floats2half2_rn(v.x, v.y);
            hp[1] = __floats2half2_rn(v.z, v.w);
        }
        #pragma unroll
        for (int o = 16; o; o >>= 1) s += __shfl_xor_sync(0xFFFFFFFFu, s, o);
        if (lane == 0) g_cw[row] = s;
    } else {
        int r = row - BB * NN;
        const float* src = qry + (size_t)r * DD;
        float s = 0.f;
        #pragma unroll
        for (int d = lane * 4; d < DD; d += 128) {
            float4 v  = *(const float4*)(src + d);
            float4 wv = *(const float4*)(w + d);
            s += v.x * wv.x + v.y * wv.y + v.z * wv.z + v.w * wv.w;
        }
        #pragma unroll
        for (int o = 16; o; o >>= 1) s += __shfl_xor_sync(0xFFFFFFFFu, s, o);
        if (lane == 0) g_qw[r] = s;
    }
}

// ----- k_q: one pass over qry -> qT[d][m] fp16 (transposed) + qs[m][d] fp16 ------
__global__ void k_q(const float* __restrict__ qry, const float* __restrict__ w) {
    __shared__ float t[32][33];
    int b = blockIdx.z, m0 = blockIdx.x * 32, d0 = blockIdx.y * 32;
    int tx = threadIdx.x, ty = threadIdx.y;
    const float* src = qry + ((size_t)b * MM + m0) * DD + d0;
    float wmv = w[2 * DD + d0 + tx];
    #pragma unroll
    for (int i = 0; i < 4; i++) {
        float v = src[(size_t)(ty + 8 * i) * DD + tx];
        t[ty + 8 * i][tx] = v;
        g_qs[((size_t)b * MM + m0 + ty + 8 * i) * DD + d0 + tx] = __float2half_rn(v * wmv);
    }
    __syncthreads();
    __half* dst = g_qT + ((size_t)b * DD + d0) * MM + m0;
    #pragma unroll
    for (int i = 0; i < 4; i++)
        dst[(size_t)(ty + 8 * i) * MM + tx] = __float2half_rn(t[tx][ty + 8 * i]);
}

// ============ k_S_f: S = ctx.qs^T (64n x 256m), 256thr, 2-stage ==================
// Epilogue anchored at column max over ALL block rows (fc always finite):
// E = exp(s-fc) (0 stored for invalid rows); A = E*exp(fc)/rowsum(E*exp(fc)).
#define S_STGB 46080               // (64 + 256) * 144
#define S_BOFFB 9216               // 64 * 144
#define S_REDF (2 * S_STGB / 4)
__global__ void __launch_bounds__(256) k_S_f() {
    extern __shared__ float sm[];
    float* rowred  = sm + S_REDF;          // [4][64]
    float* colred  = rowred + 256;         // [2][256]
    float* colred2 = colred + 512;         // [2][256]
    float* cw_s    = colred2 + 512;        // [64]
    float* qw_s    = cw_s + 64;            // [256]

    int b = blockIdx.y, n0 = blockIdx.x * 64;
    int tid = threadIdx.x, lane = tid & 31, warp = tid >> 5;
    int wn = warp & 1, wm = warp >> 1;
    uint32_t smb = s2u(sm);

    if (tid < 64) cw_s[tid] = g_cw[b * NN + n0 + tid];
    qw_s[tid] = g_qw[b * MM + tid];

    const __half* ctxb = g_ctxh + ((size_t)b * NN + n0) * DD;
    const __half* qsb  = g_qs   + (size_t)b * MM * DD;

    uint32_t aLd[2], bLd[4];
    #pragma unroll
    for (int i = 0; i < 2; i++)
        aLd[i] = smb + (wn * 32 + i * 16 + (lane & 15)) * 144 + (lane >> 4) * 16;
    #pragma unroll
    for (int jj = 0; jj < 4; jj++)
        bLd[jj] = smb + S_BOFFB + (wm * 64 + jj * 16 + (lane & 15)) * 144 + (lane >> 4) * 16;

    float acc[2][8][4] = {};
    const int KT = DD / 64;  // 8

    #define SF_LOAD(kt, s) do { \
        uint32_t base = smb + (s) * S_STGB; \
        _Pragma("unroll") \
        for (int r2 = 0; r2 < 2; r2++) { \
            int idx = tid + 256 * r2; int row = idx >> 3, c = idx & 7; \
            cp16(base + row * 144 + c * 16, ctxb + (size_t)row * DD + (kt) * 64 + c * 8); \
        } \
        _Pragma("unroll") \
        for (int r2 = 0; r2 < 8; r2++) { \
            int idx = tid + 256 * r2; int row = idx >> 3, c = idx & 7; \
            cp16(base + S_BOFFB + row * 144 + c * 16, qsb + (size_t)row * DD + (kt) * 64 + c * 8); \
        } \
    } while (0)

    SF_LOAD(0, 0); cp_commit();

    for (int kt = 0; kt < KT; kt++) {
        if (kt + 1 < KT) { SF_LOAD(kt + 1, (kt + 1) & 1); cp_commit(); cp_wait1(); }
        else             { cp_wait0(); }
        __syncthreads();
        uint32_t boff = (kt & 1) * S_STGB;
        #pragma unroll
        for (int kk = 0; kk < 4; kk++) {
            uint32_t ko = boff + kk * 32;
            uint32_t a0[4], a1[4];
            ldsm4(a0, aLd[0] + ko);
            ldsm4(a1, aLd[1] + ko);
            #pragma unroll
            for (int jj = 0; jj < 4; jj++) {
                uint32_t bb[4];
                ldsm4(bb, bLd[jj] + ko);
                mma16(acc[0][2 * jj],     a0, bb[0], bb[2]);
                mma16(acc[0][2 * jj + 1], a0, bb[1], bb[3]);
                mma16(acc[1][2 * jj],     a1, bb[0], bb[2]);
                mma16(acc[1][2 * jj + 1], a1, bb[1], bb[3]);
            }
        }
        __syncthreads();
    }
    #undef SF_LOAD

    // ======== fused epilogue (col-max anchored, fc over ALL rows) ========
    int qlen = g_qlen[b], clen = g_clen[b];
    int rbase = wn * 32 + (lane >> 2);
    int cbase = wm * 64 + 2 * (lane & 3);

    // pass 1: per-column block max over ALL 64 rows (finite always)
    #pragma unroll
    for (int j = 0; j < 8; j++) {
        #pragma unroll
        for (int e2 = 0; e2 < 2; e2++) {
            int c = cbase + j * 8 + e2;
            float cm = -1e30f;
            #pragma unroll
            for (int i = 0; i < 2; i++)
                #pragma unroll
                for (int h = 0; h < 2; h++) {
                    int r = rbase + i * 16 + h * 8;
                    cm = fmaxf(cm, acc[i][j][h * 2 + e2] + cw_s[r] + qw_s[c]);
                }
            #pragma unroll
            for (int o = 4; o <= 16; o <<= 1)
                cm = fmaxf(cm, __shfl_xor_sync(0xFFFFFFFFu, cm, o));
            if ((lane >> 2) == 0) colred[wn * 256 + c] = cm;
        }
    }
    __syncthreads();

    // pass 2: E = exp(s - fc) (kept in acc), E store (0 if invalid row),
    //         col sums (valid rows only), row sums of E*exp(fc) (all rows)
    float uc[8][2];
    float rs[2][2] = {};
    #pragma unroll
    for (int j = 0; j < 8; j++) {
        int c = cbase + j * 8;
        float fc0 = fmaxf(colred[c],     colred[256 + c]);
        float fc1 = fmaxf(colred[c + 1], colred[256 + c + 1]);
        uc[j][0] = __expf(fc0);
        uc[j][1] = __expf(fc1);
        bool q0 = (c < qlen), q1 = (c + 1 < qlen);
        float cs0 = 0.f, cs1 = 0.f;
        #pragma unroll
        for (int i = 0; i < 2; i++)
            #pragma unroll
            for (int h = 0; h < 2; h++) {
                int r = rbase + i * 16 + h * 8;
                bool valid = (n0 + r < clen);
                float cwv = cw_s[r];
                float e0 = __expf(acc[i][j][h * 2]     + cwv + qw_s[c]     - fc0);
                float e1 = __expf(acc[i][j][h * 2 + 1] + cwv + qw_s[c + 1] - fc1);
                acc[i][j][h * 2]     = e0;
                acc[i][j][h * 2 + 1] = e1;
                __half* Erow = g_E + ((size_t)b * NN + n0 + r) * MM;
                *(__half2*)(Erow + c) = __floats2half2_rn(valid ? e0 : 0.f, valid ? e1 : 0.f);
                if (valid) { cs0 += e0; cs1 += e1; }
                rs[i][h] += (q0 ? e0 * uc[j][0] : 0.f) + (q1 ? e1 * uc[j][1] : 0.f);
            }
        #pragma unroll
        for (int o = 4; o <= 16; o <<= 1) {
            cs0 += __shfl_xor_sync(0xFFFFFFFFu, cs0, o);
            cs1 += __shfl_xor_sync(0xFFFFFFFFu, cs1, o);
        }
        if ((lane >> 2) == 0) {
            colred2[wn * 256 + c]     = cs0;
            colred2[wn * 256 + c + 1] = cs1;
        }
    }
    #pragma unroll
    for (int i = 0; i < 2; i++)
        #pragma unroll
        for (int h = 0; h < 2; h++) {
            #pragma unroll
            for (int o = 1; o <= 2; o <<= 1)
                rs[i][h] += __shfl_xor_sync(0xFFFFFFFFu, rs[i][h], o);
        }
    if ((lane & 3) == 0) {
        #pragma unroll
        for (int i = 0; i < 2; i++)
            #pragma unroll
            for (int h = 0; h < 2; h++)
                rowred[wm * 64 + rbase + i * 16 + h * 8] = rs[i][h];
    }
    __syncthreads();

    // pass 3a: column partials to global
    if (wn == 0 && (lane >> 2) == 0) {
        #pragma unroll
        for (int j = 0; j < 8; j++)
            #pragma unroll
            for (int e2 = 0; e2 < 2; e2++) {
                int c = cbase + j * 8 + e2;
                float fm2 = fmaxf(colred[c], colred[256 + c]);
                float ps  = colred2[c] + colred2[256 + c];
                g_pmax[b][blockIdx.x][c] = fm2;
                g_psum[b][blockIdx.x][c] = ps;
            }
    }

    // pass 3b: rinv and A = E * uc * rinv
    float rinv[2][2];
    #pragma unroll
    for (int i = 0; i < 2; i++)
        #pragma unroll
        for (int h = 0; h < 2; h++) {
            int r = rbase + i * 16 + h * 8;
            float t = 0.f;
            #pragma unroll
            for (int q = 0; q < 4; q++) t += rowred[q * 64 + r];
            rinv[i][h] = 1.f / t;
        }
    #pragma unroll
    for (int i = 0; i < 2; i++)
        #pragma unroll
        for (int h = 0; h < 2; h++) {
            int r = rbase + i * 16 + h * 8;
            __half* Arow = g_A + ((size_t)b * NN + n0 + r) * MM;
            #pragma unroll
            for (int j = 0; j < 8; j++) {
                int c = cbase + j * 8;
                float a0 = (c < qlen)     ? acc[i][j][h * 2]     * uc[j][0] * rinv[i][h] : 0.f;
                float a1 = (c + 1 < qlen) ? acc[i][j][h * 2 + 1] * uc[j][1] * rinv[i][h] : 0.f;
                *(__half2*)(Arow + c) = __floats2half2_rn(a0, a1);
            }
        }
}

// ==== k_mid_f: midT[d][m] = ((E*sc)^T @ ctx)^T, 256thr, 128m x 128d, BK=64 =======
// warps: wm = warp&3 (32m), wd = warp>>2 (64d, 4 bLd blocks).
#define M_STGB 34816               // E 64x272 (17408) + ctx 64x272 (17408)
#define M_BOFFB 17408
__global__ void __launch_bounds__(256, 2) k_mid_f() {
    extern __shared__ float sm[];
    uint32_t smb = s2u(sm);
    uint32_t* scs = (uint32_t*)((char*)sm + 2 * M_STGB);   // [NSPLIT][128]

    int b = blockIdx.z, d0 = blockIdx.x * 128, m0 = blockIdx.y * 128;
    int tid = threadIdx.x, lane = tid & 31, warp = tid >> 5;
    int wm = warp & 3, wd = warp >> 2;

    if (tid < 128) {
        int m = m0 + tid;
        float fm = -1e30f;
        #pragma unroll
        for (int q = 0; q < NSPLIT; q++) fm = fmaxf(fm, g_pmax[b][q][m]);
        float fs = 0.f;
        #pragma unroll
        for (int q = 0; q < NSPLIT; q++)
            fs += g_psum[b][q][m] * __expf(g_pmax[b][q][m] - fm);
        float inv = 1.f / fs;
        #pragma unroll
        for (int q = 0; q < NSPLIT; q++) {
            float s = __expf(g_pmax[b][q][m] - fm) * inv;
            __half2 h2 = __half2half2(__float2half_rn(s));
            scs[q * 128 + tid] = *(uint32_t*)&h2;
        }
    }

    const __half* Eb   = g_E    + (size_t)b * NN * MM;
    const __half* ctxb = g_ctxh + (size_t)b * NN * DD;

    int lr = lane & 7, g = lane >> 3;
    uint32_t aLd[2], bLd[4];
    #pragma unroll
    for (int i = 0; i < 2; i++)
        aLd[i] = smb + (lr + (g >> 1) * 8) * 272 + (wm * 32 + i * 16 + (g & 1) * 8) * 2;
    #pragma unroll
    for (int j = 0; j < 4; j++)
        bLd[j] = smb + M_BOFFB + (lr + (g & 1) * 8) * 272 + (wd * 64 + j * 16 + (g >> 1) * 8) * 2;

    float acc[2][8][4] = {};
    const int KT = NN / 64;  // 16

    #define MF_LOAD(kt, s) do { \
        uint32_t base = smb + (s) * M_STGB; \
        _Pragma("unroll") \
        for (int r2 = 0; r2 < 4; r2++) { \
            int idx = tid + 256 * r2; int row = idx >> 4, c = idx & 15; \
            cp16(base + row * 272 + c * 16, Eb + (size_t)((kt) * 64 + row) * MM + m0 + c * 8); \
            cp16(base + M_BOFFB + row * 272 + c * 16, ctxb + (size_t)((kt) * 64 + row) * DD + d0 + c * 8); \
        } \
    } while (0)

    MF_LOAD(0, 0); cp_commit();

    for (int kt = 0; kt < KT; kt++) {
        if (kt + 1 < KT) { MF_LOAD(kt + 1, (kt + 1) & 1); cp_commit(); cp_wait1(); }
        else             { cp_wait0(); }
        __syncthreads();
        uint32_t base = (kt & 1) * M_STGB;
        uint32_t sc00 = scs[kt * 128 + wm * 32 + (lane >> 2)];
        uint32_t sc01 = scs[kt * 128 + wm * 32 + (lane >> 2) + 8];
        uint32_t sc10 = scs[kt * 128 + wm * 32 + 16 + (lane >> 2)];
        uint32_t sc11 = scs[kt * 128 + wm * 32 + 16 + (lane >> 2) + 8];
        #pragma unroll
        for (int step = 0; step < 4; step++) {
            uint32_t koA = base + step * 16 * 272;
            uint32_t a[2][4];
            ldsm4t(a[0], aLd[0] + koA);
            ldsm4t(a[1], aLd[1] + koA);
            a[0][0] = hmul2u(a[0][0], sc00); a[0][2] = hmul2u(a[0][2], sc00);
            a[0][1] = hmul2u(a[0][1], sc01); a[0][3] = hmul2u(a[0][3], sc01);
            a[1][0] = hmul2u(a[1][0], sc10); a[1][2] = hmul2u(a[1][2], sc10);
            a[1][1] = hmul2u(a[1][1], sc11); a[1][3] = hmul2u(a[1][3], sc11);
            #pragma unroll
            for (int j = 0; j < 4; j++) {
                uint32_t bb[4];
                ldsm4t(bb, bLd[j] + koA);
                #pragma unroll
                for (int i = 0; i < 2; i++) {
                    mma16(acc[i][j * 2],     a[i], bb[0], bb[1]);
                    mma16(acc[i][j * 2 + 1], a[i], bb[2], bb[3]);
                }
            }
        }
        __syncthreads();
    }
    #undef MF_LOAD

    // epilogue: stage fp16 [d][m] (stride 136 halfs), coalesced store
    __half* ot = (__half*)sm;
    #pragma unroll
    for (int i = 0; i < 2; i++) {
        int m_r = wm * 32 + i * 16 + (lane >> 2);
        #pragma unroll
        for (int jj = 0; jj < 8; jj++) {
            int c = wd * 64 + jj * 8 + 2 * (lane & 3);
            ot[(size_t)c * 136 + m_r]           = __float2half_rn(acc[i][jj][0]);
            ot[(size_t)(c + 1) * 136 + m_r]     = __float2half_rn(acc[i][jj][1]);
            ot[(size_t)c * 136 + m_r + 8]       = __float2half_rn(acc[i][jj][2]);
            ot[(size_t)(c + 1) * 136 + m_r + 8] = __float2half_rn(acc[i][jj][3]);
        }
    }
    __syncthreads();
    #pragma unroll
    for (int rep = 0; rep < 8; rep++) {
        int idx = tid + rep * 256;
        int d = idx >> 4, m8 = (idx & 15) * 8;
        uint4 v = *(uint4*)(ot + (size_t)d * 136 + m8);
        *(uint4*)(g_midT + ((size_t)b * DD + d0 + d) * MM + m0 + m8) = v;
    }
}

// ======== k_out_f: c2q/q2c, 256thr, 128n x 64d dual, 2-stage (R15 winner) =======
#define O_STGB 36864
#define O_QOFFB 18432
#define O_MOFFB 27648
__global__ void __launch_bounds__(256) k_out_f(const float* __restrict__ ctx,
                                               float* __restrict__ out) {
    extern __shared__ float sm[];
    int b = blockIdx.z, d0 = blockIdx.x * 64, n0 = blockIdx.y * 128;
    int tid = threadIdx.x, lane = tid & 31, warp = tid >> 5;
    int wn = warp & 3, wd = warp >> 2;
    uint32_t smb = s2u(sm);

    const __half* Ab  = g_A    + ((size_t)b * NN + n0) * MM;
    const __half* qTb = g_qT   + ((size_t)b * DD + d0) * MM;
    const __half* mTb = g_midT + ((size_t)b * DD + d0) * MM;

    uint32_t aLd[2], bqLd[2], bmLd[2];
    #pragma unroll
    for (int i = 0; i < 2; i++)
        aLd[i] = smb + (wn * 32 + i * 16 + (lane & 15)) * 144 + (lane >> 4) * 16;
    #pragma unroll
    for (int jj = 0; jj < 2; jj++) {
        bqLd[jj] = smb + O_QOFFB + (wd * 32 + jj * 16 + (lane & 15)) * 144 + (lane >> 4) * 16;
        bmLd[jj] = smb + O_MOFFB + (wd * 32 + jj * 16 + (lane & 15)) * 144 + (lane >> 4) * 16;
    }

    float accq[2][4][4] = {};
    float accm[2][4][4] = {};
    const int KT = MM / 64;  // 4

    #define OF_LOAD(kt, s) do { \
        uint32_t base = smb + (s) * O_STGB; \
        _Pragma("unroll") \
        for (int r2 = 0; r2 < 4; r2++) { \
            int idx = tid + 256 * r2; int row = idx >> 3, c = idx & 7; \
            cp16(base + row * 144 + c * 16, Ab + (size_t)row * MM + (kt) * 64 + c * 8); \
        } \
        _Pragma("unroll") \
        for (int r2 = 0; r2 < 2; r2++) { \
            int idx = tid + 256 * r2; int row = idx >> 3, c = idx & 7; \
            uint32_t o = row * 144 + c * 16; \
            cp16(base + O_QOFFB + o, qTb + (size_t)row * MM + (kt) * 64 + c * 8); \
            cp16(base + O_MOFFB + o, mTb + (size_t)row * MM + (kt) * 64 + c * 8); \
        } \
    } while (0)

    OF_LOAD(0, 0); cp_commit();

    for (int kt = 0; kt < KT; kt++) {
        if (kt + 1 < KT) { OF_LOAD(kt + 1, (kt + 1) & 1); cp_commit(); cp_wait1(); }
        else             { cp_wait0(); }
        __syncthreads();
        uint32_t boff = (kt & 1) * O_STGB;
        #pragma unroll
        for (int kk = 0; kk < 4; kk++) {
            uint32_t ko = boff + kk * 32;
            uint32_t a0[4], a1[4];
            ldsm4(a0, aLd[0] + ko);
            ldsm4(a1, aLd[1] + ko);
            #pragma unroll
            for (int jj = 0; jj < 2; jj++) {
                uint32_t bq[4], bm[4];
                ldsm4(bq, bqLd[jj] + ko);
                mma16(accq[0][jj * 2],     a0, bq[0], bq[2]);
                mma16(accq[0][jj * 2 + 1], a0, bq[1], bq[3]);
                mma16(accq[1][jj * 2],     a1, bq[0], bq[2]);
                mma16(accq[1][jj * 2 + 1], a1, bq[1], bq[3]);
                ldsm4(bm, bmLd[jj] + ko);
                mma16(accm[0][jj * 2],     a0, bm[0], bm[2]);
                mma16(accm[0][jj * 2 + 1], a0, bm[1], bm[3]);
                mma16(accm[1][jj * 2],     a1, bm[0], bm[2]);
                mma16(accm[1][jj * 2 + 1], a1, bm[1], bm[3]);
            }
        }
        __syncthreads();
    }
    #undef OF_LOAD

    // epilogue: out = [ctx, c2q, ctx*c2q, ctx*q2c]
    #pragma unroll
    for (int i = 0; i < 2; i++) {
        #pragma unroll
        for (int half = 0; half < 2; half++) {
            int n = n0 + wn * 32 + i * 16 + (lane >> 2) + half * 8;
            const float* crow = ctx + ((size_t)b * NN + n) * DD;
            float* orow = out + ((size_t)b * NN + n) * (4 * DD);
            #pragma unroll
            for (int ai = 0; ai < 4; ai++) {
                int d = d0 + wd * 32 + ai * 8 + 2 * (lane & 3);
                float2 cv = *(const float2*)(crow + d);
                float c2q0 = accq[i][ai][half * 2], c2q1 = accq[i][ai][half * 2 + 1];
                float q2c0 = accm[i][ai][half * 2], q2c1 = accm[i][ai][half * 2 + 1];
                *(float2*)(orow + d)          = cv;
                *(float2*)(orow + DD + d)     = make_float2(c2q0, c2q1);
                *(float2*)(orow + 2 * DD + d) = make_float2(cv.x * c2q0, cv.y * c2q1);
                *(float2*)(orow + 3 * DD + d) = make_float2(cv.x * q2c0, cv.y * q2c1);
            }
        }
    }
}

// -------------------- launch --------------------
extern "C" void kernel_launch(void* const* d_in, const int* in_sizes, int n_in,
                              void* d_out, int out_size) {
    const float* ctx = (const float*)d_in[0];
    const float* qry = (const float*)d_in[1];
    const unsigned char* cm = (const unsigned char*)d_in[2];
    const unsigned char* qm = (const unsigned char*)d_in[3];
    const float* w = (const float*)d_in[4];
    float* out = (float*)d_out;

    const int SMEM_S   = 2 * S_STGB + 1600 * 4;               // 98560
    const int SMEM_MID = 2 * M_STGB + NSPLIT * 128 * 4;       // 77824
    const int SMEM_OUT = 2 * O_STGB;                          // 73728

    cudaFuncSetAttribute(k_S_f,   cudaFuncAttributeMaxDynamicSharedMemorySize, SMEM_S);
    cudaFuncSetAttribute(k_mid_f, cudaFuncAttributeMaxDynamicSharedMemorySize, SMEM_MID);
    cudaFuncSetAttribute(k_out_f, cudaFuncAttributeMaxDynamicSharedMemorySize, SMEM_OUT);

    k_lens<<<1, 64>>>(cm, qm);
    k_rowdots<<<(BB * NN + BB * MM) / 8, 256>>>(ctx, qry, w);
    k_q<<<dim3(MM / 32, DD / 32, BB), dim3(32, 8)>>>(qry, w);
    k_S_f<<<dim3(NN / 64, BB), 256, SMEM_S>>>();
    k_mid_f<<<dim3(DD / 128, MM / 128, BB), 256, SMEM_MID>>>();
    k_out_f<<<dim3(DD / 64, NN / 128, BB), 256, SMEM_OUT>>>(ctx, out);
}